// round 7
// baseline (speedup 1.0000x reference)
#include <cuda_runtime.h>
#include <cuda_fp16.h>
#include <cstdint>

#define DIM 1024
#define M_TOTAL 8192
#define N_TOTAL 3072
#define RANK 16

// ---------------- scratch (module-static device arrays; no runtime alloc) ----
__device__ __half g_X16[(size_t)M_TOTAL * DIM];   // 16 MB fp16 activations
__device__ __half g_W16[(size_t)N_TOTAL * DIM];   // 6 MB fp16 merged weights

// ---------------- PTX helpers (baseline ISA only: sm_80-era) ------------------
__device__ __forceinline__ uint32_t smem_u32(const void* p) {
    uint32_t a;
    asm("{ .reg .u64 t; cvta.to.shared.u64 t, %1; cvt.u32.u64 %0, t; }" : "=r"(a) : "l"(p));
    return a;
}

#define CP_ASYNC16(dst_smem, src_g) \
    asm volatile("cp.async.cg.shared.global [%0], [%1], 16;" :: "r"(dst_smem), "l"(src_g) : "memory")
#define CP_ASYNC_COMMIT() asm volatile("cp.async.commit_group;" ::: "memory")
#define CP_ASYNC_WAIT(n)  asm volatile("cp.async.wait_group %0;" :: "n"(n) : "memory")

__device__ __forceinline__ void ldmatrix_x4(uint32_t* r, uint32_t addr) {
    asm volatile("ldmatrix.sync.aligned.m8n8.x4.shared.b16 {%0,%1,%2,%3}, [%4];"
                 : "=r"(r[0]), "=r"(r[1]), "=r"(r[2]), "=r"(r[3]) : "r"(addr));
}

__device__ __forceinline__ void mma16816(float* c, const uint32_t* a,
                                         uint32_t b0, uint32_t b1) {
    asm volatile(
        "mma.sync.aligned.m16n8k16.row.col.f32.f16.f16.f32 "
        "{%0,%1,%2,%3}, {%4,%5,%6,%7}, {%8,%9}, {%0,%1,%2,%3};"
        : "+f"(c[0]), "+f"(c[1]), "+f"(c[2]), "+f"(c[3])
        : "r"(a[0]), "r"(a[1]), "r"(a[2]), "r"(a[3]), "r"(b0), "r"(b1));
}

// ---------------- fused prep kernel -------------------------------------------
// Blocks [0, 192): W' = W + alpha * B@A -> fp16 (128x128 tile each, first)
// Blocks [192, 192+4096): x fp32 -> fp16 (8 elems/thread, vectorized)
#define WPREP_BLOCKS ((N_TOTAL / 128) * (DIM / 128))   // 192
#define CONVERT_BLOCKS 4096

__global__ void __launch_bounds__(256)
prep_kernel(const float* __restrict__ x, const float* __restrict__ W,
            const float* __restrict__ Aq, const float* __restrict__ Bq,
            const float* __restrict__ Ak, const float* __restrict__ Bk,
            const float* __restrict__ Av, const float* __restrict__ Bv,
            const float* __restrict__ alpha_p) {
    int tid = threadIdx.x;
    if (blockIdx.x >= WPREP_BLOCKS) {
        size_t i = ((size_t)(blockIdx.x - WPREP_BLOCKS) * 256 + tid) * 8;
        float4 a = *reinterpret_cast<const float4*>(x + i);
        float4 b = *reinterpret_cast<const float4*>(x + i + 4);
        __half2 h[4];
        h[0] = __floats2half2_rn(a.x, a.y);
        h[1] = __floats2half2_rn(a.z, a.w);
        h[2] = __floats2half2_rn(b.x, b.y);
        h[3] = __floats2half2_rn(b.z, b.w);
        *reinterpret_cast<uint4*>(g_X16 + i) = *reinterpret_cast<uint4*>(h);
        return;
    }
    __shared__ float sA[RANK][128];   // A_seg[r][k]
    __shared__ float sB[128][RANK];   // B_seg[d][r]
    int idx = blockIdx.x;
    int n0 = (idx % (N_TOTAL / 128)) * 128;
    int k0 = (idx / (N_TOTAL / 128)) * 128;
    int seg = n0 >> 10;
    int nl0 = n0 & 1023;
    const float* A = (seg == 0) ? Aq : (seg == 1) ? Ak : Av;
    const float* B = (seg == 0) ? Bq : (seg == 1) ? Bk : Bv;
    for (int i = tid; i < RANK * 128; i += 256)
        sA[i >> 7][i & 127] = A[(size_t)(i >> 7) * DIM + k0 + (i & 127)];
    for (int i = tid; i < 128 * RANK; i += 256)
        sB[i >> 4][i & 15] = B[(size_t)(nl0 + (i >> 4)) * RANK + (i & 15)];
    __syncthreads();
    float al = *alpha_p;
    for (int e = tid; e < 128 * 128; e += 256) {
        int d = e >> 7, c = e & 127;
        float acc = 0.f;
#pragma unroll
        for (int r = 0; r < RANK; r++) acc += sB[d][r] * sA[r][c];
        size_t gi = (size_t)(n0 + d) * DIM + k0 + c;
        g_W16[gi] = __float2half_rn(W[gi] + al * acc);
    }
}

// ---------------- GEMM: HMMA (mma.sync) + bias epilogue -----------------------
// out[M,N] = X16[M,K] @ W16[N,K]^T + bias ;  M=8192 N=3072 K=1024
// CTA tile 128x128 with 128 threads (2x2 warps), warp tile 64x64, occupancy 2.
// Register double-buffering of fragments across ks steps: LDSM(ks+1) issues
// BEFORE the MMAs(ks), so the frozen volatile-asm order interleaves ~32
// independent HMMA between LDSM issue and consumption -> pipes overlap.
#define BM 128
#define BN 128
#define BK 64
#define KCHUNKS (DIM / BK)                 // 16
#define STAGE_BYTES (BM * 128 + BN * 128)  // 32768
#define NSTAGES 3
#define GEMM_SMEM (NSTAGES * STAGE_BYTES)  // 98304

// 16B-chunk XOR swizzle: chunk' = chunk ^ (row & 7) -> conflict-free ldmatrix.
__device__ __forceinline__ void load_stage(uint32_t sb, int tid,
                                           const char* gA, const char* gB,
                                           int kc, int s) {
    uint32_t sa = sb + s * STAGE_BYTES;
    uint32_t sbb = sa + BM * 128;
    const char* a = gA + kc * (BK * 2);
    const char* b = gB + kc * (BK * 2);
#pragma unroll
    for (int i = 0; i < 8; i++) {          // 128 rows x 8 chunks, 128 threads
        int seg = i * 128 + tid;
        int r = seg >> 3, ch = seg & 7;
        CP_ASYNC16(sa + r * 128 + ((ch ^ (r & 7)) << 4),
                   a + (size_t)r * (DIM * 2) + ch * 16);
    }
#pragma unroll
    for (int i = 0; i < 8; i++) {
        int seg = i * 128 + tid;
        int r = seg >> 3, ch = seg & 7;
        CP_ASYNC16(sbb + r * 128 + ((ch ^ (r & 7)) << 4),
                   b + (size_t)r * (DIM * 2) + ch * 16);
    }
}

__global__ void __launch_bounds__(128, 2)
gemm_kernel(const float* __restrict__ bias, float* __restrict__ out) {
    extern __shared__ char smem[];
    uint32_t sb = smem_u32(smem);
    const int tid = threadIdx.x, wid = tid >> 5, lane = tid & 31;
    const int m0 = blockIdx.y * BM, n0 = blockIdx.x * BN;
    const int wm = wid >> 1;   // 0..1 -> 64 rows each
    const int wn = wid & 1;    // 0..1 -> 64 cols each

    const char* gA = (const char*)(g_X16 + (size_t)m0 * DIM);
    const char* gB = (const char*)(g_W16 + (size_t)n0 * DIM);

    float c[4][8][4];
#pragma unroll
    for (int i = 0; i < 4; i++)
#pragma unroll
        for (int j = 0; j < 8; j++)
#pragma unroll
            for (int k = 0; k < 4; k++) c[i][j][k] = 0.f;

    const int lrow = (lane & 7) + ((lane >> 3) & 1) * 8;  // row within 16-row tile
    const int lch = (lane >> 4);                           // 0/1: 16B chunk half

    // precomputed swizzled row-base offsets (row-constant across ks)
    uint32_t abase[4], bbase[4];
#pragma unroll
    for (int t = 0; t < 4; t++) {
        abase[t] = (wm * 64 + t * 16 + lrow) * 128;
        bbase[t] = (wn * 64 + t * 16 + lrow) * 128;
    }

    uint32_t af[2][4][4], bf[2][4][4];

    load_stage(sb, tid, gA, gB, 0, 0);
    CP_ASYNC_COMMIT();
    load_stage(sb, tid, gA, gB, 1, 1);
    CP_ASYNC_COMMIT();

    for (int kc = 0; kc < KCHUNKS; kc++) {
        if (kc + 2 < KCHUNKS) CP_ASYNC_WAIT(1);
        else                  CP_ASYNC_WAIT(0);
        __syncthreads();

        if (kc + 2 < KCHUNKS) {
            load_stage(sb, tid, gA, gB, kc + 2, (kc + 2) % NSTAGES);
            CP_ASYNC_COMMIT();
        }

        uint32_t sa = sb + (kc % NSTAGES) * STAGE_BYTES;
        uint32_t sbb = sa + BM * 128;

        // prime ks=0 fragments into buffer 0
        {
            int ch = lch;  // 2*0 + lch
#pragma unroll
            for (int mt = 0; mt < 4; mt++) {
                int r16 = wm * 64 + mt * 16 + lrow;
                ldmatrix_x4(af[0][mt], sa + abase[mt] + (((ch) ^ (r16 & 7)) << 4));
            }
#pragma unroll
            for (int nt = 0; nt < 4; nt++) {
                int r16 = wn * 64 + nt * 16 + lrow;
                ldmatrix_x4(bf[0][nt], sbb + bbase[nt] + (((ch) ^ (r16 & 7)) << 4));
            }
        }

#pragma unroll
        for (int ks = 0; ks < 4; ks++) {
            int cur = ks & 1;
            if (ks < 3) {                    // prefetch ks+1 BEFORE consuming ks
                int nxt = (ks + 1) & 1;
                int ch = 2 * (ks + 1) + lch;
#pragma unroll
                for (int mt = 0; mt < 4; mt++) {
                    int r16 = wm * 64 + mt * 16 + lrow;
                    ldmatrix_x4(af[nxt][mt], sa + abase[mt] + ((ch ^ (r16 & 7)) << 4));
                }
#pragma unroll
                for (int nt = 0; nt < 4; nt++) {
                    int r16 = wn * 64 + nt * 16 + lrow;
                    ldmatrix_x4(bf[nxt][nt], sbb + bbase[nt] + ((ch ^ (r16 & 7)) << 4));
                }
            }
#pragma unroll
            for (int mt = 0; mt < 4; mt++)
#pragma unroll
                for (int n8 = 0; n8 < 8; n8++) {
                    int nt = n8 >> 1, hi = n8 & 1;
                    mma16816(c[mt][n8], af[cur][mt], bf[cur][nt][hi], bf[cur][nt][2 + hi]);
                }
        }
    }

    // ------- epilogue: +bias, direct float2 stores -------
#pragma unroll
    for (int n8 = 0; n8 < 8; n8++) {
        int n = n0 + wn * 64 + n8 * 8 + ((lane & 3) << 1);
        float bv0 = bias[n], bv1 = bias[n + 1];
#pragma unroll
        for (int mt = 0; mt < 4; mt++) {
            int m = m0 + wm * 64 + mt * 16 + (lane >> 2);
            float2 v0 = make_float2(c[mt][n8][0] + bv0, c[mt][n8][1] + bv1);
            float2 v1 = make_float2(c[mt][n8][2] + bv0, c[mt][n8][3] + bv1);
            *reinterpret_cast<float2*>(out + (size_t)m * N_TOTAL + n) = v0;
            *reinterpret_cast<float2*>(out + (size_t)(m + 8) * N_TOTAL + n) = v1;
        }
    }
}

// ---------------- launch -------------------------------------------------------
extern "C" void kernel_launch(void* const* d_in, const int* in_sizes, int n_in,
                              void* d_out, int out_size) {
    const float* x     = (const float*)d_in[0];
    const float* W_qkv = (const float*)d_in[1];
    const float* b_qkv = (const float*)d_in[2];
    const float* A_q   = (const float*)d_in[3];
    const float* B_q   = (const float*)d_in[4];
    const float* A_k   = (const float*)d_in[5];
    const float* B_k   = (const float*)d_in[6];
    const float* A_v   = (const float*)d_in[7];
    const float* B_v   = (const float*)d_in[8];
    const float* alpha = (const float*)d_in[9];
    float* out = (float*)d_out;

    static bool attr_done = false;
    if (!attr_done) {
        cudaFuncSetAttribute(gemm_kernel, cudaFuncAttributeMaxDynamicSharedMemorySize, GEMM_SMEM);
        attr_done = true;
    }

    prep_kernel<<<WPREP_BLOCKS + CONVERT_BLOCKS, 256>>>(
        x, W_qkv, A_q, B_q, A_k, B_k, A_v, B_v, alpha);
    gemm_kernel<<<dim3(N_TOTAL / BN, M_TOTAL / BM), 128, GEMM_SMEM>>>(b_qkv, out);
}

// round 8
// speedup vs baseline: 1.0467x; 1.0467x over previous
#include <cuda_runtime.h>
#include <cuda_fp16.h>
#include <cstdint>

#define DIM 1024
#define M_TOTAL 8192
#define N_TOTAL 3072
#define RANK 16

// ---------------- scratch (module-static device arrays; no runtime alloc) ----
__device__ __half g_X16[(size_t)M_TOTAL * DIM];   // 16 MB fp16 activations
__device__ __half g_W16[(size_t)N_TOTAL * DIM];   // 6 MB fp16 merged weights

// ---------------- PTX helpers (baseline ISA only: sm_80-era) ------------------
__device__ __forceinline__ uint32_t smem_u32(const void* p) {
    uint32_t a;
    asm("{ .reg .u64 t; cvta.to.shared.u64 t, %1; cvt.u32.u64 %0, t; }" : "=r"(a) : "l"(p));
    return a;
}

#define CP_ASYNC16(dst_smem, src_g) \
    asm volatile("cp.async.cg.shared.global [%0], [%1], 16;" :: "r"(dst_smem), "l"(src_g) : "memory")
#define CP_ASYNC_COMMIT() asm volatile("cp.async.commit_group;" ::: "memory")
#define CP_ASYNC_WAIT(n)  asm volatile("cp.async.wait_group %0;" :: "n"(n) : "memory")

__device__ __forceinline__ void ldmatrix_x4(uint32_t* r, uint32_t addr) {
    asm volatile("ldmatrix.sync.aligned.m8n8.x4.shared.b16 {%0,%1,%2,%3}, [%4];"
                 : "=r"(r[0]), "=r"(r[1]), "=r"(r[2]), "=r"(r[3]) : "r"(addr));
}

__device__ __forceinline__ void mma16816(float* c, const uint32_t* a,
                                         uint32_t b0, uint32_t b1) {
    asm volatile(
        "mma.sync.aligned.m16n8k16.row.col.f32.f16.f16.f32 "
        "{%0,%1,%2,%3}, {%4,%5,%6,%7}, {%8,%9}, {%0,%1,%2,%3};"
        : "+f"(c[0]), "+f"(c[1]), "+f"(c[2]), "+f"(c[3])
        : "r"(a[0]), "r"(a[1]), "r"(a[2]), "r"(a[3]), "r"(b0), "r"(b1));
}

// ---------------- fused prep kernel -------------------------------------------
// Blocks [0, 192): W' = W + alpha * B@A -> fp16 (128x128 tile each, first)
// Blocks [192, 192+4096): x fp32 -> fp16 (8 elems/thread, vectorized)
#define WPREP_BLOCKS ((N_TOTAL / 128) * (DIM / 128))   // 192
#define CONVERT_BLOCKS 4096

__global__ void __launch_bounds__(256)
prep_kernel(const float* __restrict__ x, const float* __restrict__ W,
            const float* __restrict__ Aq, const float* __restrict__ Bq,
            const float* __restrict__ Ak, const float* __restrict__ Bk,
            const float* __restrict__ Av, const float* __restrict__ Bv,
            const float* __restrict__ alpha_p) {
    int tid = threadIdx.x;
    if (blockIdx.x >= WPREP_BLOCKS) {
        size_t i = ((size_t)(blockIdx.x - WPREP_BLOCKS) * 256 + tid) * 8;
        float4 a = *reinterpret_cast<const float4*>(x + i);
        float4 b = *reinterpret_cast<const float4*>(x + i + 4);
        __half2 h[4];
        h[0] = __floats2half2_rn(a.x, a.y);
        h[1] = __floats2half2_rn(a.z, a.w);
        h[2] = __floats2half2_rn(b.x, b.y);
        h[3] = __floats2half2_rn(b.z, b.w);
        *reinterpret_cast<uint4*>(g_X16 + i) = *reinterpret_cast<uint4*>(h);
        return;
    }
    __shared__ float sA[RANK][128];   // A_seg[r][k]
    __shared__ float sB[128][RANK];   // B_seg[d][r]
    int idx = blockIdx.x;
    int n0 = (idx % (N_TOTAL / 128)) * 128;
    int k0 = (idx / (N_TOTAL / 128)) * 128;
    int seg = n0 >> 10;
    int nl0 = n0 & 1023;
    const float* A = (seg == 0) ? Aq : (seg == 1) ? Ak : Av;
    const float* B = (seg == 0) ? Bq : (seg == 1) ? Bk : Bv;
    for (int i = tid; i < RANK * 128; i += 256)
        sA[i >> 7][i & 127] = A[(size_t)(i >> 7) * DIM + k0 + (i & 127)];
    for (int i = tid; i < 128 * RANK; i += 256)
        sB[i >> 4][i & 15] = B[(size_t)(nl0 + (i >> 4)) * RANK + (i & 15)];
    __syncthreads();
    float al = *alpha_p;
    for (int e = tid; e < 128 * 128; e += 256) {
        int d = e >> 7, c = e & 127;
        float acc = 0.f;
#pragma unroll
        for (int r = 0; r < RANK; r++) acc += sB[d][r] * sA[r][c];
        size_t gi = (size_t)(n0 + d) * DIM + k0 + c;
        g_W16[gi] = __float2half_rn(W[gi] + al * acc);
    }
}

// ---------------- GEMM: HMMA (mma.sync) + bias epilogue -----------------------
// out[M,N] = X16[M,K] @ W16[N,K]^T + bias ;  M=8192 N=3072 K=1024
// CTA tile 64x128 with 128 threads (2x2 warps), warp tile 32x64, OCCUPANCY 3.
// Grid 3072 CTAs -> 6.92 waves at 444 concurrent = 98.8% wave efficiency
// (vs 86.5% for the 1536-CTA/occ-2 config), targeting the per-SM HMMA rate
// wall identified in R5-R7.
#define BM 64
#define BN 128
#define BK 64
#define KCHUNKS (DIM / BK)                 // 16
#define STAGE_BYTES (BM * 128 + BN * 128)  // 24576
#define NSTAGES 3
#define GEMM_SMEM (NSTAGES * STAGE_BYTES)  // 73728

// 16B-chunk XOR swizzle: chunk' = chunk ^ (row & 7) -> conflict-free ldmatrix.
__device__ __forceinline__ void load_stage(uint32_t sb, int tid,
                                           const char* gA, const char* gB,
                                           int kc, int s) {
    uint32_t sa = sb + s * STAGE_BYTES;
    uint32_t sbb = sa + BM * 128;
    const char* a = gA + kc * (BK * 2);
    const char* b = gB + kc * (BK * 2);
#pragma unroll
    for (int i = 0; i < 4; i++) {          // A: 64 rows x 8 chunks, 128 threads
        int seg = i * 128 + tid;
        int r = seg >> 3, ch = seg & 7;
        CP_ASYNC16(sa + r * 128 + ((ch ^ (r & 7)) << 4),
                   a + (size_t)r * (DIM * 2) + ch * 16);
    }
#pragma unroll
    for (int i = 0; i < 8; i++) {          // B: 128 rows x 8 chunks
        int seg = i * 128 + tid;
        int r = seg >> 3, ch = seg & 7;
        CP_ASYNC16(sbb + r * 128 + ((ch ^ (r & 7)) << 4),
                   b + (size_t)r * (DIM * 2) + ch * 16);
    }
}

__global__ void __launch_bounds__(128, 3)
gemm_kernel(const float* __restrict__ bias, float* __restrict__ out) {
    extern __shared__ char smem[];
    uint32_t sb = smem_u32(smem);
    const int tid = threadIdx.x, wid = tid >> 5, lane = tid & 31;
    const int m0 = blockIdx.y * BM, n0 = blockIdx.x * BN;
    const int wm = wid >> 1;   // 0..1 -> 32 rows each
    const int wn = wid & 1;    // 0..1 -> 64 cols each

    const char* gA = (const char*)(g_X16 + (size_t)m0 * DIM);
    const char* gB = (const char*)(g_W16 + (size_t)n0 * DIM);

    float c[2][8][4];
#pragma unroll
    for (int i = 0; i < 2; i++)
#pragma unroll
        for (int j = 0; j < 8; j++)
#pragma unroll
            for (int k = 0; k < 4; k++) c[i][j][k] = 0.f;

    const int lrow = (lane & 7) + ((lane >> 3) & 1) * 8;  // row within 16-row tile
    const int lch = (lane >> 4);                           // 0/1: 16B chunk half

    load_stage(sb, tid, gA, gB, 0, 0);
    CP_ASYNC_COMMIT();
    load_stage(sb, tid, gA, gB, 1, 1);
    CP_ASYNC_COMMIT();

    for (int kc = 0; kc < KCHUNKS; kc++) {
        if (kc + 2 < KCHUNKS) CP_ASYNC_WAIT(1);
        else                  CP_ASYNC_WAIT(0);
        __syncthreads();

        if (kc + 2 < KCHUNKS) {
            load_stage(sb, tid, gA, gB, kc + 2, (kc + 2) % NSTAGES);
            CP_ASYNC_COMMIT();
        }

        uint32_t sa = sb + (kc % NSTAGES) * STAGE_BYTES;
        uint32_t sbb = sa + BM * 128;

#pragma unroll
        for (int ks = 0; ks < 4; ks++) {
            int ch = 2 * ks + lch;
            uint32_t af[2][4];
#pragma unroll
            for (int mt = 0; mt < 2; mt++) {
                int r = wm * 32 + mt * 16 + lrow;
                ldmatrix_x4(af[mt], sa + r * 128 + ((ch ^ (r & 7)) << 4));
            }
            uint32_t bf[4][4];
#pragma unroll
            for (int nt = 0; nt < 4; nt++) {
                int r = wn * 64 + nt * 16 + lrow;
                ldmatrix_x4(bf[nt], sbb + r * 128 + ((ch ^ (r & 7)) << 4));
            }
#pragma unroll
            for (int mt = 0; mt < 2; mt++)
#pragma unroll
                for (int n8 = 0; n8 < 8; n8++) {
                    int nt = n8 >> 1, hi = n8 & 1;
                    mma16816(c[mt][n8], af[mt], bf[nt][hi], bf[nt][2 + hi]);
                }
        }
    }

    // ------- epilogue: +bias, direct float2 stores -------
#pragma unroll
    for (int n8 = 0; n8 < 8; n8++) {
        int n = n0 + wn * 64 + n8 * 8 + ((lane & 3) << 1);
        float bv0 = bias[n], bv1 = bias[n + 1];
#pragma unroll
        for (int mt = 0; mt < 2; mt++) {
            int m = m0 + wm * 32 + mt * 16 + (lane >> 2);
            float2 v0 = make_float2(c[mt][n8][0] + bv0, c[mt][n8][1] + bv1);
            float2 v1 = make_float2(c[mt][n8][2] + bv0, c[mt][n8][3] + bv1);
            *reinterpret_cast<float2*>(out + (size_t)m * N_TOTAL + n) = v0;
            *reinterpret_cast<float2*>(out + (size_t)(m + 8) * N_TOTAL + n) = v1;
        }
    }
}

// ---------------- launch -------------------------------------------------------
extern "C" void kernel_launch(void* const* d_in, const int* in_sizes, int n_in,
                              void* d_out, int out_size) {
    const float* x     = (const float*)d_in[0];
    const float* W_qkv = (const float*)d_in[1];
    const float* b_qkv = (const float*)d_in[2];
    const float* A_q   = (const float*)d_in[3];
    const float* B_q   = (const float*)d_in[4];
    const float* A_k   = (const float*)d_in[5];
    const float* B_k   = (const float*)d_in[6];
    const float* A_v   = (const float*)d_in[7];
    const float* B_v   = (const float*)d_in[8];
    const float* alpha = (const float*)d_in[9];
    float* out = (float*)d_out;

    static bool attr_done = false;
    if (!attr_done) {
        cudaFuncSetAttribute(gemm_kernel, cudaFuncAttributeMaxDynamicSharedMemorySize, GEMM_SMEM);
        attr_done = true;
    }

    prep_kernel<<<WPREP_BLOCKS + CONVERT_BLOCKS, 256>>>(
        x, W_qkv, A_q, B_q, A_k, B_k, A_v, B_v, alpha);
    gemm_kernel<<<dim3(N_TOTAL / BN, M_TOTAL / BM), 128, GEMM_SMEM>>>(b_qkv, out);
}

// round 9
// speedup vs baseline: 1.1332x; 1.0826x over previous
#include <cuda_runtime.h>
#include <cuda_fp16.h>
#include <cstdint>

#define DIM 1024
#define M_TOTAL 8192
#define N_TOTAL 3072
#define RANK 16

// ---------------- scratch (module-static device arrays; no runtime alloc) ----
__device__ __half g_X16[(size_t)M_TOTAL * DIM];   // 16 MB fp16 activations
__device__ __half g_W16[(size_t)N_TOTAL * DIM];   // 6 MB fp16 merged weights

// ---------------- PTX helpers (baseline ISA only: sm_80-era) ------------------
__device__ __forceinline__ uint32_t smem_u32(const void* p) {
    uint32_t a;
    asm("{ .reg .u64 t; cvta.to.shared.u64 t, %1; cvt.u32.u64 %0, t; }" : "=r"(a) : "l"(p));
    return a;
}

#define CP_ASYNC16(dst_smem, src_g) \
    asm volatile("cp.async.cg.shared.global [%0], [%1], 16;" :: "r"(dst_smem), "l"(src_g) : "memory")
#define CP_ASYNC_COMMIT() asm volatile("cp.async.commit_group;" ::: "memory")
#define CP_ASYNC_WAIT(n)  asm volatile("cp.async.wait_group %0;" :: "n"(n) : "memory")

__device__ __forceinline__ void ldmatrix_x4(uint32_t* r, uint32_t addr) {
    asm volatile("ldmatrix.sync.aligned.m8n8.x4.shared.b16 {%0,%1,%2,%3}, [%4];"
                 : "=r"(r[0]), "=r"(r[1]), "=r"(r[2]), "=r"(r[3]) : "r"(addr));
}

__device__ __forceinline__ void mma16816(float* c, const uint32_t* a,
                                         uint32_t b0, uint32_t b1) {
    asm volatile(
        "mma.sync.aligned.m16n8k16.row.col.f32.f16.f16.f32 "
        "{%0,%1,%2,%3}, {%4,%5,%6,%7}, {%8,%9}, {%0,%1,%2,%3};"
        : "+f"(c[0]), "+f"(c[1]), "+f"(c[2]), "+f"(c[3])
        : "r"(a[0]), "r"(a[1]), "r"(a[2]), "r"(a[3]), "r"(b0), "r"(b1));
}

// ---------------- fused prep kernel -------------------------------------------
// Blocks [0, 384): W' = W + alpha * B@A -> fp16 (128x64 tile each, first)
// Blocks [384, 384+2048): x fp32 -> fp16 (16 elems/thread, vectorized)
#define WPREP_BLOCKS ((N_TOTAL / 128) * (DIM / 64))   // 24 * 16 = 384
#define CONVERT_BLOCKS ((M_TOTAL * DIM) / (256 * 16)) // 2048

__global__ void __launch_bounds__(256)
prep_kernel(const float* __restrict__ x, const float* __restrict__ W,
            const float* __restrict__ Aq, const float* __restrict__ Bq,
            const float* __restrict__ Ak, const float* __restrict__ Bk,
            const float* __restrict__ Av, const float* __restrict__ Bv,
            const float* __restrict__ alpha_p) {
    int tid = threadIdx.x;
    if (blockIdx.x >= WPREP_BLOCKS) {
        size_t i = ((size_t)(blockIdx.x - WPREP_BLOCKS) * 256 + tid) * 16;
        float4 a0 = *reinterpret_cast<const float4*>(x + i);
        float4 a1 = *reinterpret_cast<const float4*>(x + i + 4);
        float4 a2 = *reinterpret_cast<const float4*>(x + i + 8);
        float4 a3 = *reinterpret_cast<const float4*>(x + i + 12);
        __half2 h[8];
        h[0] = __floats2half2_rn(a0.x, a0.y);
        h[1] = __floats2half2_rn(a0.z, a0.w);
        h[2] = __floats2half2_rn(a1.x, a1.y);
        h[3] = __floats2half2_rn(a1.z, a1.w);
        h[4] = __floats2half2_rn(a2.x, a2.y);
        h[5] = __floats2half2_rn(a2.z, a2.w);
        h[6] = __floats2half2_rn(a3.x, a3.y);
        h[7] = __floats2half2_rn(a3.z, a3.w);
        *reinterpret_cast<uint4*>(g_X16 + i)     = *reinterpret_cast<uint4*>(h);
        *reinterpret_cast<uint4*>(g_X16 + i + 8) = *reinterpret_cast<uint4*>(h + 4);
        return;
    }
    __shared__ float sA[RANK][64];    // A_seg[r][k]   (k-tile = 64)
    __shared__ float sB[128][RANK];   // B_seg[d][r]
    int idx = blockIdx.x;
    int n0 = (idx % (N_TOTAL / 128)) * 128;
    int k0 = (idx / (N_TOTAL / 128)) * 64;
    int seg = n0 >> 10;
    int nl0 = n0 & 1023;
    const float* A = (seg == 0) ? Aq : (seg == 1) ? Ak : Av;
    const float* B = (seg == 0) ? Bq : (seg == 1) ? Bk : Bv;
    for (int i = tid; i < RANK * 64; i += 256)
        sA[i >> 6][i & 63] = A[(size_t)(i >> 6) * DIM + k0 + (i & 63)];
    for (int i = tid; i < 128 * RANK; i += 256)
        sB[i >> 4][i & 15] = B[(size_t)(nl0 + (i >> 4)) * RANK + (i & 15)];
    __syncthreads();
    float al = *alpha_p;
    for (int e = tid; e < 128 * 64; e += 256) {
        int d = e >> 6, c = e & 63;
        float acc = 0.f;
#pragma unroll
        for (int r = 0; r < RANK; r++) acc += sB[d][r] * sA[r][c];
        size_t gi = (size_t)(n0 + d) * DIM + k0 + c;
        g_W16[gi] = __float2half_rn(W[gi] + al * acc);
    }
}

// ---------------- GEMM: HMMA (mma.sync) + bias epilogue -----------------------
// out[M,N] = X16[M,K] @ W16[N,K]^T + bias ;  M=8192 N=3072 K=1024
// CTA tile 64x128, 128 threads (2x2 warps), warp tile 32x64, occupancy 3.
// All kc-invariant address math hoisted into registers: cp.async uses
// precomputed (global, swizzled-smem) offset pairs; ldmatrix addresses use
// the decomposition ((2ks+lch)^s)<<4 = ((lch^(s&1))<<4) + ((ks<<5)^((s&6)<<4))
// so each inner address is LOP3-imm + IADD off a per-kc row base.
#define BM 64
#define BN 128
#define BK 64
#define KCHUNKS (DIM / BK)                 // 16
#define STAGE_BYTES (BM * 128 + BN * 128)  // 24576
#define NSTAGES 3
#define GEMM_SMEM (NSTAGES * STAGE_BYTES)  // 73728

__global__ void __launch_bounds__(128, 3)
gemm_kernel(const float* __restrict__ bias, float* __restrict__ out) {
    extern __shared__ char smem[];
    uint32_t sb = smem_u32(smem);
    const int tid = threadIdx.x, wid = tid >> 5, lane = tid & 31;
    const int m0 = blockIdx.y * BM, n0 = blockIdx.x * BN;
    const int wm = wid >> 1;   // 0..1 -> 32 rows each
    const int wn = wid & 1;    // 0..1 -> 64 cols each

    const char* gA = (const char*)(g_X16 + (size_t)m0 * DIM);
    const char* gB = (const char*)(g_W16 + (size_t)n0 * DIM);

    // ---- hoisted cp.async offsets (kc-invariant) ----
    uint32_t ag[4], asw[4], bg[8], bsw[8];
#pragma unroll
    for (int i = 0; i < 4; i++) {          // A: 64 rows x 8 chunks
        int seg = i * 128 + tid;
        int r = seg >> 3, ch = seg & 7;
        ag[i]  = (uint32_t)(r * (DIM * 2) + ch * 16);
        asw[i] = (uint32_t)(r * 128 + ((ch ^ (r & 7)) << 4));
    }
#pragma unroll
    for (int i = 0; i < 8; i++) {          // B: 128 rows x 8 chunks
        int seg = i * 128 + tid;
        int r = seg >> 3, ch = seg & 7;
        bg[i]  = (uint32_t)(r * (DIM * 2) + ch * 16);
        bsw[i] = (uint32_t)(r * 128 + ((ch ^ (r & 7)) << 4));
    }

    // ---- hoisted ldmatrix bases ----
    const int lrow = (lane & 7) + ((lane >> 3) & 1) * 8;
    const int lch = lane >> 4;
    uint32_t aB[2], aX[2], bB[4], bX[4];
#pragma unroll
    for (int mt = 0; mt < 2; mt++) {
        int r = wm * 32 + mt * 16 + lrow, s = r & 7;
        aB[mt] = (uint32_t)(r * 128 + ((lch ^ (s & 1)) << 4));
        aX[mt] = (uint32_t)((s & 6) << 4);
    }
#pragma unroll
    for (int nt = 0; nt < 4; nt++) {
        int r = wn * 64 + nt * 16 + lrow, s = r & 7;
        bB[nt] = (uint32_t)(r * 128 + ((lch ^ (s & 1)) << 4));
        bX[nt] = (uint32_t)((s & 6) << 4);
    }

    float c[2][8][4];
#pragma unroll
    for (int i = 0; i < 2; i++)
#pragma unroll
        for (int j = 0; j < 8; j++)
#pragma unroll
            for (int k = 0; k < 4; k++) c[i][j][k] = 0.f;

    // ---- pipeline ----
#pragma unroll
    for (int p = 0; p < 2; p++) {          // prologue: chunks 0,1
        uint32_t sa = sb + p * STAGE_BYTES;
        uint32_t sbb = sa + BM * 128;
        const char* a = gA + p * (BK * 2);
        const char* b = gB + p * (BK * 2);
#pragma unroll
        for (int i = 0; i < 4; i++) CP_ASYNC16(sa + asw[i], a + ag[i]);
#pragma unroll
        for (int i = 0; i < 8; i++) CP_ASYNC16(sbb + bsw[i], b + bg[i]);
        CP_ASYNC_COMMIT();
    }

    for (int kc = 0; kc < KCHUNKS; kc++) {
        if (kc + 2 < KCHUNKS) CP_ASYNC_WAIT(1);
        else                  CP_ASYNC_WAIT(0);
        __syncthreads();

        if (kc + 2 < KCHUNKS) {
            int s = (kc + 2) % NSTAGES;
            uint32_t sa = sb + s * STAGE_BYTES;
            uint32_t sbb = sa + BM * 128;
            const char* a = gA + (kc + 2) * (BK * 2);
            const char* b = gB + (kc + 2) * (BK * 2);
#pragma unroll
            for (int i = 0; i < 4; i++) CP_ASYNC16(sa + asw[i], a + ag[i]);
#pragma unroll
            for (int i = 0; i < 8; i++) CP_ASYNC16(sbb + bsw[i], b + bg[i]);
            CP_ASYNC_COMMIT();
        }

        uint32_t sa = sb + (kc % NSTAGES) * STAGE_BYTES;
        uint32_t sbb = sa + BM * 128;
        // per-kc row bases (stage-dependent)
        uint32_t arb[2], brb[4];
#pragma unroll
        for (int mt = 0; mt < 2; mt++) arb[mt] = sa + aB[mt];
#pragma unroll
        for (int nt = 0; nt < 4; nt++) brb[nt] = sbb + bB[nt];

#pragma unroll
        for (int ks = 0; ks < 4; ks++) {
            const uint32_t ko = (uint32_t)(ks << 5);
            uint32_t af[2][4];
#pragma unroll
            for (int mt = 0; mt < 2; mt++)
                ldmatrix_x4(af[mt], arb[mt] + (ko ^ aX[mt]));
            uint32_t bf[4][4];
#pragma unroll
            for (int nt = 0; nt < 4; nt++)
                ldmatrix_x4(bf[nt], brb[nt] + (ko ^ bX[nt]));
#pragma unroll
            for (int mt = 0; mt < 2; mt++)
#pragma unroll
                for (int n8 = 0; n8 < 8; n8++) {
                    int nt = n8 >> 1, hi = n8 & 1;
                    mma16816(c[mt][n8], af[mt], bf[nt][hi], bf[nt][2 + hi]);
                }
        }
    }

    // ------- epilogue: +bias, direct float2 stores -------
#pragma unroll
    for (int n8 = 0; n8 < 8; n8++) {
        int n = n0 + wn * 64 + n8 * 8 + ((lane & 3) << 1);
        float bv0 = bias[n], bv1 = bias[n + 1];
#pragma unroll
        for (int mt = 0; mt < 2; mt++) {
            int m = m0 + wm * 32 + mt * 16 + (lane >> 2);
            float2 v0 = make_float2(c[mt][n8][0] + bv0, c[mt][n8][1] + bv1);
            float2 v1 = make_float2(c[mt][n8][2] + bv0, c[mt][n8][3] + bv1);
            *reinterpret_cast<float2*>(out + (size_t)m * N_TOTAL + n) = v0;
            *reinterpret_cast<float2*>(out + (size_t)(m + 8) * N_TOTAL + n) = v1;
        }
    }
}

// ---------------- launch -------------------------------------------------------
extern "C" void kernel_launch(void* const* d_in, const int* in_sizes, int n_in,
                              void* d_out, int out_size) {
    const float* x     = (const float*)d_in[0];
    const float* W_qkv = (const float*)d_in[1];
    const float* b_qkv = (const float*)d_in[2];
    const float* A_q   = (const float*)d_in[3];
    const float* B_q   = (const float*)d_in[4];
    const float* A_k   = (const float*)d_in[5];
    const float* B_k   = (const float*)d_in[6];
    const float* A_v   = (const float*)d_in[7];
    const float* B_v   = (const float*)d_in[8];
    const float* alpha = (const float*)d_in[9];
    float* out = (float*)d_out;

    static bool attr_done = false;
    if (!attr_done) {
        cudaFuncSetAttribute(gemm_kernel, cudaFuncAttributeMaxDynamicSharedMemorySize, GEMM_SMEM);
        attr_done = true;
    }

    prep_kernel<<<WPREP_BLOCKS + CONVERT_BLOCKS, 256>>>(
        x, W_qkv, A_q, B_q, A_k, B_k, A_v, B_v, alpha);
    gemm_kernel<<<dim3(N_TOTAL / BN, M_TOTAL / BM), 128, GEMM_SMEM>>>(b_qkv, out);
}

// round 10
// speedup vs baseline: 1.1398x; 1.0058x over previous
#include <cuda_runtime.h>
#include <cuda_fp16.h>
#include <cstdint>

#define DIM 1024
#define M_TOTAL 8192
#define N_TOTAL 3072
#define RANK 16

// ---------------- scratch (module-static device arrays; no runtime alloc) ----
__device__ __half g_X16[(size_t)M_TOTAL * DIM];   // 16 MB fp16 activations
__device__ __half g_W16[(size_t)N_TOTAL * DIM];   // 6 MB fp16 merged weights

// ---------------- PTX helpers (baseline ISA only: sm_80-era) ------------------
__device__ __forceinline__ uint32_t smem_u32(const void* p) {
    uint32_t a;
    asm("{ .reg .u64 t; cvta.to.shared.u64 t, %1; cvt.u32.u64 %0, t; }" : "=r"(a) : "l"(p));
    return a;
}

#define CP_ASYNC16(dst_smem, src_g) \
    asm volatile("cp.async.cg.shared.global [%0], [%1], 16;" :: "r"(dst_smem), "l"(src_g) : "memory")
#define CP_ASYNC_COMMIT() asm volatile("cp.async.commit_group;" ::: "memory")
#define CP_ASYNC_WAIT(n)  asm volatile("cp.async.wait_group %0;" :: "n"(n) : "memory")

__device__ __forceinline__ void ldmatrix_x4(uint32_t* r, uint32_t addr) {
    asm volatile("ldmatrix.sync.aligned.m8n8.x4.shared.b16 {%0,%1,%2,%3}, [%4];"
                 : "=r"(r[0]), "=r"(r[1]), "=r"(r[2]), "=r"(r[3]) : "r"(addr));
}

__device__ __forceinline__ void mma16816(float* c, const uint32_t* a,
                                         uint32_t b0, uint32_t b1) {
    asm volatile(
        "mma.sync.aligned.m16n8k16.row.col.f32.f16.f16.f32 "
        "{%0,%1,%2,%3}, {%4,%5,%6,%7}, {%8,%9}, {%0,%1,%2,%3};"
        : "+f"(c[0]), "+f"(c[1]), "+f"(c[2]), "+f"(c[3])
        : "r"(a[0]), "r"(a[1]), "r"(a[2]), "r"(a[3]), "r"(b0), "r"(b1));
}

// ---------------- fused prep kernel -------------------------------------------
#define WPREP_BLOCKS ((N_TOTAL / 128) * (DIM / 64))   // 384
#define CONVERT_BLOCKS ((M_TOTAL * DIM) / (256 * 16)) // 2048

__global__ void __launch_bounds__(256)
prep_kernel(const float* __restrict__ x, const float* __restrict__ W,
            const float* __restrict__ Aq, const float* __restrict__ Bq,
            const float* __restrict__ Ak, const float* __restrict__ Bk,
            const float* __restrict__ Av, const float* __restrict__ Bv,
            const float* __restrict__ alpha_p) {
    int tid = threadIdx.x;
    if (blockIdx.x >= WPREP_BLOCKS) {
        size_t i = ((size_t)(blockIdx.x - WPREP_BLOCKS) * 256 + tid) * 16;
        float4 a0 = *reinterpret_cast<const float4*>(x + i);
        float4 a1 = *reinterpret_cast<const float4*>(x + i + 4);
        float4 a2 = *reinterpret_cast<const float4*>(x + i + 8);
        float4 a3 = *reinterpret_cast<const float4*>(x + i + 12);
        __half2 h[8];
        h[0] = __floats2half2_rn(a0.x, a0.y);
        h[1] = __floats2half2_rn(a0.z, a0.w);
        h[2] = __floats2half2_rn(a1.x, a1.y);
        h[3] = __floats2half2_rn(a1.z, a1.w);
        h[4] = __floats2half2_rn(a2.x, a2.y);
        h[5] = __floats2half2_rn(a2.z, a2.w);
        h[6] = __floats2half2_rn(a3.x, a3.y);
        h[7] = __floats2half2_rn(a3.z, a3.w);
        *reinterpret_cast<uint4*>(g_X16 + i)     = *reinterpret_cast<uint4*>(h);
        *reinterpret_cast<uint4*>(g_X16 + i + 8) = *reinterpret_cast<uint4*>(h + 4);
        return;
    }
    __shared__ float sA[RANK][64];
    __shared__ float sB[128][RANK];
    int idx = blockIdx.x;
    int n0 = (idx % (N_TOTAL / 128)) * 128;
    int k0 = (idx / (N_TOTAL / 128)) * 64;
    int seg = n0 >> 10;
    int nl0 = n0 & 1023;
    const float* A = (seg == 0) ? Aq : (seg == 1) ? Ak : Av;
    const float* B = (seg == 0) ? Bq : (seg == 1) ? Bk : Bv;
    for (int i = tid; i < RANK * 64; i += 256)
        sA[i >> 6][i & 63] = A[(size_t)(i >> 6) * DIM + k0 + (i & 63)];
    for (int i = tid; i < 128 * RANK; i += 256)
        sB[i >> 4][i & 15] = B[(size_t)(nl0 + (i >> 4)) * RANK + (i & 15)];
    __syncthreads();
    float al = *alpha_p;
    for (int e = tid; e < 128 * 64; e += 256) {
        int d = e >> 6, c = e & 63;
        float acc = 0.f;
#pragma unroll
        for (int r = 0; r < RANK; r++) acc += sB[d][r] * sA[r][c];
        size_t gi = (size_t)(n0 + d) * DIM + k0 + c;
        g_W16[gi] = __float2half_rn(W[gi] + al * acc);
    }
}

// ---------------- GEMM: HMMA (mma.sync) + bias epilogue -----------------------
// out[M,N] = X16[M,K] @ W16[N,K]^T + bias ;  M=8192 N=3072 K=1024
// CTA 64x128, 128 threads (2x2 warps), warp tile 32x64, occupancy 3.
// R10: register fragment double-buffering (LDSM(ks+1) before MMA(ks)),
// cp.async offsets as single base + immediate strides (24 regs -> 2),
// cp.async items spread 3-per-ks to smooth LSU/port pressure.
#define BM 64
#define BN 128
#define BK 64
#define KCHUNKS (DIM / BK)                 // 16
#define STAGE_BYTES (BM * 128 + BN * 128)  // 24576
#define NSTAGES 3
#define GEMM_SMEM (NSTAGES * STAGE_BYTES)  // 73728

__global__ void __launch_bounds__(128, 3)
gemm_kernel(const float* __restrict__ bias, float* __restrict__ out) {
    extern __shared__ char smem[];
    uint32_t sb = smem_u32(smem);
    const int tid = threadIdx.x, wid = tid >> 5, lane = tid & 31;
    const int m0 = blockIdx.y * BM, n0 = blockIdx.x * BN;
    const int wm = wid >> 1;   // 0..1 -> 32 rows each
    const int wn = wid & 1;    // 0..1 -> 64 cols each

    const char* gA = (const char*)(g_X16 + (size_t)m0 * DIM);
    const char* gB = (const char*)(g_W16 + (size_t)n0 * DIM);

    // cp.async base offsets: A and B share the identical per-thread mapping;
    // item i is base + i*2048 (smem) / base + i*32768 (global).
    const int cr = tid >> 3, cc = tid & 7;
    const uint32_t g0  = (uint32_t)(cr * (DIM * 2) + cc * 16);
    const uint32_t sw0 = (uint32_t)(cr * 128 + ((cc ^ (cr & 7)) << 4));

    // hoisted ldmatrix bases
    const int lrow = (lane & 7) + ((lane >> 3) & 1) * 8;
    const int lch = lane >> 4;
    uint32_t aB[2], aX[2], bB[4], bX[4];
#pragma unroll
    for (int mt = 0; mt < 2; mt++) {
        int r = wm * 32 + mt * 16 + lrow, s = r & 7;
        aB[mt] = (uint32_t)(r * 128 + ((lch ^ (s & 1)) << 4));
        aX[mt] = (uint32_t)((s & 6) << 4);
    }
#pragma unroll
    for (int nt = 0; nt < 4; nt++) {
        int r = wn * 64 + nt * 16 + lrow, s = r & 7;
        bB[nt] = (uint32_t)(r * 128 + ((lch ^ (s & 1)) << 4));
        bX[nt] = (uint32_t)((s & 6) << 4);
    }

    float c[2][8][4];
#pragma unroll
    for (int i = 0; i < 2; i++)
#pragma unroll
        for (int j = 0; j < 8; j++)
#pragma unroll
            for (int k = 0; k < 4; k++) c[i][j][k] = 0.f;

    // ---- prologue: chunks 0,1 ----
#pragma unroll
    for (int p = 0; p < 2; p++) {
        uint32_t sa = sb + p * STAGE_BYTES;
        uint32_t sbb = sa + BM * 128;
        const char* a = gA + p * (BK * 2);
        const char* b = gB + p * (BK * 2);
#pragma unroll
        for (int i = 0; i < 4; i++) CP_ASYNC16(sa + sw0 + i * 2048, a + g0 + i * 32768);
#pragma unroll
        for (int i = 0; i < 8; i++) CP_ASYNC16(sbb + sw0 + i * 2048, b + g0 + i * 32768);
        CP_ASYNC_COMMIT();
    }

    uint32_t af[2][2][4], bf[2][4][4];

    for (int kc = 0; kc < KCHUNKS; kc++) {
        if (kc + 2 < KCHUNKS) CP_ASYNC_WAIT(1);
        else                  CP_ASYNC_WAIT(0);
        __syncthreads();

        uint32_t sa = sb + (kc % NSTAGES) * STAGE_BYTES;
        uint32_t sbb = sa + BM * 128;
        uint32_t arb[2], brb[4];
#pragma unroll
        for (int mt = 0; mt < 2; mt++) arb[mt] = sa + aB[mt];
#pragma unroll
        for (int nt = 0; nt < 4; nt++) brb[nt] = sbb + bB[nt];

        // prime ks=0 fragments into buffer 0
#pragma unroll
        for (int mt = 0; mt < 2; mt++) ldmatrix_x4(af[0][mt], arb[mt] + (0u ^ aX[mt]));
#pragma unroll
        for (int nt = 0; nt < 4; nt++) ldmatrix_x4(bf[0][nt], brb[nt] + (0u ^ bX[nt]));

        const bool pf = (kc + 2 < KCHUNKS);
        uint32_t sa2 = sb + ((kc + 2) % NSTAGES) * STAGE_BYTES;
        uint32_t sb2 = sa2 + BM * 128;
        const char* a2 = gA + (kc + 2) * (BK * 2);
        const char* b2 = gB + (kc + 2) * (BK * 2);

#pragma unroll
        for (int ks = 0; ks < 4; ks++) {
            const int cur = ks & 1, nxt = cur ^ 1;
            if (ks < 3) {                     // prefetch frags for ks+1
                const uint32_t ko = (uint32_t)((ks + 1) << 5);
#pragma unroll
                for (int mt = 0; mt < 2; mt++)
                    ldmatrix_x4(af[nxt][mt], arb[mt] + (ko ^ aX[mt]));
#pragma unroll
                for (int nt = 0; nt < 4; nt++)
                    ldmatrix_x4(bf[nxt][nt], brb[nt] + (ko ^ bX[nt]));
            }
            if (pf) {                          // 3 cp.async items per ks (12 total)
#pragma unroll
                for (int j = 3 * ks; j < 3 * ks + 3; j++) {
                    if (j < 4) CP_ASYNC16(sa2 + sw0 + j * 2048, a2 + g0 + (size_t)j * 32768);
                    else       CP_ASYNC16(sb2 + sw0 + (j - 4) * 2048, b2 + g0 + (size_t)(j - 4) * 32768);
                }
            }
#pragma unroll
            for (int mt = 0; mt < 2; mt++)
#pragma unroll
                for (int n8 = 0; n8 < 8; n8++) {
                    int nt = n8 >> 1, hi = n8 & 1;
                    mma16816(c[mt][n8], af[cur][mt], bf[cur][nt][hi], bf[cur][nt][2 + hi]);
                }
        }
        if (pf) CP_ASYNC_COMMIT();
    }

    // ------- epilogue: +bias, direct float2 stores -------
#pragma unroll
    for (int n8 = 0; n8 < 8; n8++) {
        int n = n0 + wn * 64 + n8 * 8 + ((lane & 3) << 1);
        float bv0 = bias[n], bv1 = bias[n + 1];
#pragma unroll
        for (int mt = 0; mt < 2; mt++) {
            int m = m0 + wm * 32 + mt * 16 + (lane >> 2);
            float2 v0 = make_float2(c[mt][n8][0] + bv0, c[mt][n8][1] + bv1);
            float2 v1 = make_float2(c[mt][n8][2] + bv0, c[mt][n8][3] + bv1);
            *reinterpret_cast<float2*>(out + (size_t)m * N_TOTAL + n) = v0;
            *reinterpret_cast<float2*>(out + (size_t)(m + 8) * N_TOTAL + n) = v1;
        }
    }
}

// ---------------- launch -------------------------------------------------------
extern "C" void kernel_launch(void* const* d_in, const int* in_sizes, int n_in,
                              void* d_out, int out_size) {
    const float* x     = (const float*)d_in[0];
    const float* W_qkv = (const float*)d_in[1];
    const float* b_qkv = (const float*)d_in[2];
    const float* A_q   = (const float*)d_in[3];
    const float* B_q   = (const float*)d_in[4];
    const float* A_k   = (const float*)d_in[5];
    const float* B_k   = (const float*)d_in[6];
    const float* A_v   = (const float*)d_in[7];
    const float* B_v   = (const float*)d_in[8];
    const float* alpha = (const float*)d_in[9];
    float* out = (float*)d_out;

    static bool attr_done = false;
    if (!attr_done) {
        cudaFuncSetAttribute(gemm_kernel, cudaFuncAttributeMaxDynamicSharedMemorySize, GEMM_SMEM);
        attr_done = true;
    }

    prep_kernel<<<WPREP_BLOCKS + CONVERT_BLOCKS, 256>>>(
        x, W_qkv, A_q, B_q, A_k, B_k, A_v, B_v, alpha);
    gemm_kernel<<<dim3(N_TOTAL / BN, M_TOTAL / BM), 128, GEMM_SMEM>>>(b_qkv, out);
}

// round 11
// speedup vs baseline: 1.1511x; 1.0099x over previous
#include <cuda_runtime.h>
#include <cuda_fp16.h>
#include <cstdint>

#define DIM 1024
#define M_TOTAL 8192
#define N_TOTAL 3072
#define RANK 16

// ---------------- scratch (module-static device arrays; no runtime alloc) ----
__device__ __half g_X16[(size_t)M_TOTAL * DIM];   // 16 MB fp16 activations
__device__ __half g_W16[(size_t)N_TOTAL * DIM];   // 6 MB fp16 merged weights

// ---------------- PTX helpers (baseline ISA only: sm_80-era) ------------------
__device__ __forceinline__ uint32_t smem_u32(const void* p) {
    uint32_t a;
    asm("{ .reg .u64 t; cvta.to.shared.u64 t, %1; cvt.u32.u64 %0, t; }" : "=r"(a) : "l"(p));
    return a;
}

#define CP_ASYNC16(dst_smem, src_g) \
    asm volatile("cp.async.cg.shared.global [%0], [%1], 16;" :: "r"(dst_smem), "l"(src_g) : "memory")
#define CP_ASYNC_COMMIT() asm volatile("cp.async.commit_group;" ::: "memory")
#define CP_ASYNC_WAIT(n)  asm volatile("cp.async.wait_group %0;" :: "n"(n) : "memory")

// NON-volatile (with memory clobber): ptxas may interleave with MMAs but not
// move across barriers / cp.async.
__device__ __forceinline__ void ldmatrix_x4(uint32_t* r, uint32_t addr) {
    asm("ldmatrix.sync.aligned.m8n8.x4.shared.b16 {%0,%1,%2,%3}, [%4];"
        : "=r"(r[0]), "=r"(r[1]), "=r"(r[2]), "=r"(r[3]) : "r"(addr) : "memory");
}

// NON-volatile, register-only: fully reorderable by the scheduler.
__device__ __forceinline__ void mma16816(float* c, const uint32_t* a,
                                         uint32_t b0, uint32_t b1) {
    asm("mma.sync.aligned.m16n8k16.row.col.f32.f16.f16.f32 "
        "{%0,%1,%2,%3}, {%4,%5,%6,%7}, {%8,%9}, {%0,%1,%2,%3};"
        : "+f"(c[0]), "+f"(c[1]), "+f"(c[2]), "+f"(c[3])
        : "r"(a[0]), "r"(a[1]), "r"(a[2]), "r"(a[3]), "r"(b0), "r"(b1));
}

// ---------------- fused prep kernel -------------------------------------------
#define WPREP_BLOCKS ((N_TOTAL / 128) * (DIM / 64))   // 384
#define CONVERT_BLOCKS ((M_TOTAL * DIM) / (256 * 16)) // 2048

__global__ void __launch_bounds__(256)
prep_kernel(const float* __restrict__ x, const float* __restrict__ W,
            const float* __restrict__ Aq, const float* __restrict__ Bq,
            const float* __restrict__ Ak, const float* __restrict__ Bk,
            const float* __restrict__ Av, const float* __restrict__ Bv,
            const float* __restrict__ alpha_p) {
    int tid = threadIdx.x;
    if (blockIdx.x >= WPREP_BLOCKS) {
        size_t i = ((size_t)(blockIdx.x - WPREP_BLOCKS) * 256 + tid) * 16;
        float4 a0 = *reinterpret_cast<const float4*>(x + i);
        float4 a1 = *reinterpret_cast<const float4*>(x + i + 4);
        float4 a2 = *reinterpret_cast<const float4*>(x + i + 8);
        float4 a3 = *reinterpret_cast<const float4*>(x + i + 12);
        __half2 h[8];
        h[0] = __floats2half2_rn(a0.x, a0.y);
        h[1] = __floats2half2_rn(a0.z, a0.w);
        h[2] = __floats2half2_rn(a1.x, a1.y);
        h[3] = __floats2half2_rn(a1.z, a1.w);
        h[4] = __floats2half2_rn(a2.x, a2.y);
        h[5] = __floats2half2_rn(a2.z, a2.w);
        h[6] = __floats2half2_rn(a3.x, a3.y);
        h[7] = __floats2half2_rn(a3.z, a3.w);
        *reinterpret_cast<uint4*>(g_X16 + i)     = *reinterpret_cast<uint4*>(h);
        *reinterpret_cast<uint4*>(g_X16 + i + 8) = *reinterpret_cast<uint4*>(h + 4);
        return;
    }
    __shared__ float sA[RANK][64];
    __shared__ float sB[128][RANK];
    int idx = blockIdx.x;
    int n0 = (idx % (N_TOTAL / 128)) * 128;
    int k0 = (idx / (N_TOTAL / 128)) * 64;
    int seg = n0 >> 10;
    int nl0 = n0 & 1023;
    const float* A = (seg == 0) ? Aq : (seg == 1) ? Ak : Av;
    const float* B = (seg == 0) ? Bq : (seg == 1) ? Bk : Bv;
    for (int i = tid; i < RANK * 64; i += 256)
        sA[i >> 6][i & 63] = A[(size_t)(i >> 6) * DIM + k0 + (i & 63)];
    for (int i = tid; i < 128 * RANK; i += 256)
        sB[i >> 4][i & 15] = B[(size_t)(nl0 + (i >> 4)) * RANK + (i & 15)];
    __syncthreads();
    float al = *alpha_p;
    for (int e = tid; e < 128 * 64; e += 256) {
        int d = e >> 6, c = e & 63;
        float acc = 0.f;
#pragma unroll
        for (int r = 0; r < RANK; r++) acc += sB[d][r] * sA[r][c];
        size_t gi = (size_t)(n0 + d) * DIM + k0 + c;
        g_W16[gi] = __float2half_rn(W[gi] + al * acc);
    }
}

// ---------------- GEMM: HMMA (mma.sync) + bias epilogue -----------------------
// out[M,N] = X16[M,K] @ W16[N,K]^T + bias ;  M=8192 N=3072 K=1024
// CTA tile 128x96, 128 threads (2x2 warps), warp tile 64x48, occupancy 3
// (12 warps/SM). 2-stage cp.async pipeline, prefetch distance 1.
// Smem-port traffic per FLOP cut ~21% vs the 64x128 config.
#define BM 128
#define BN 96
#define BK 64
#define KCHUNKS (DIM / BK)                 // 16
#define STAGE_BYTES (BM * 128 + BN * 128)  // 28672
#define GEMM_SMEM (2 * STAGE_BYTES)        // 57344

__global__ void __launch_bounds__(128, 3)
gemm_kernel(const float* __restrict__ bias, float* __restrict__ out) {
    extern __shared__ char smem[];
    uint32_t sb = smem_u32(smem);
    const int tid = threadIdx.x, wid = tid >> 5, lane = tid & 31;
    const int m0 = blockIdx.y * BM, n0 = blockIdx.x * BN;
    const int wm = wid >> 1;   // 0..1 -> 64 rows each
    const int wn = wid & 1;    // 0..1 -> 48 cols each

    const char* gA = (const char*)(g_X16 + (size_t)m0 * DIM);
    const char* gB = (const char*)(g_W16 + (size_t)n0 * DIM);

    // cp.async: per-thread base; item i = base + i*2048 (smem) / +i*32768 (glob)
    const int cr = tid >> 3, cc = tid & 7;
    const uint32_t g0  = (uint32_t)(cr * (DIM * 2) + cc * 16);
    const uint32_t sw0 = (uint32_t)(cr * 128 + ((cc ^ (cr & 7)) << 4));

    // ldmatrix: row-group parity s = lrow&7 is tile-invariant -> 2 XOR regs.
    const int lrow = (lane & 7) + ((lane >> 3) & 1) * 8;
    const int lch = lane >> 4;
    const int s7 = lrow & 7;
    const uint32_t swX = (uint32_t)((s7 & 6) << 4);          // XORed with ks<<5
    const uint32_t swL = (uint32_t)((lch ^ (s7 & 1)) << 4);  // constant part
    const uint32_t aB0 = (uint32_t)((wm * 64 + lrow) * 128) + swL;          // A rows
    const uint32_t bB0 = (uint32_t)((BM + wn * 48 + lrow) * 128) + swL;     // B rows (B after A)

    float c[4][6][4];
#pragma unroll
    for (int i = 0; i < 4; i++)
#pragma unroll
        for (int j = 0; j < 6; j++)
#pragma unroll
            for (int k = 0; k < 4; k++) c[i][j][k] = 0.f;

    // ---- prologue: chunk 0 -> stage 0 ----
    {
        uint32_t sa = sb;
        uint32_t sbb = sa + BM * 128;
        const char* a = gA;
        const char* b = gB;
#pragma unroll
        for (int i = 0; i < 8; i++) CP_ASYNC16(sa + sw0 + i * 2048, a + g0 + (size_t)i * 32768);
#pragma unroll
        for (int i = 0; i < 6; i++) CP_ASYNC16(sbb + sw0 + i * 2048, b + g0 + (size_t)i * 32768);
        CP_ASYNC_COMMIT();
    }

    for (int kc = 0; kc < KCHUNKS; kc++) {
        CP_ASYNC_WAIT(0);
        __syncthreads();

        if (kc + 1 < KCHUNKS) {            // prefetch kc+1 into the other stage
            uint32_t sa = sb + ((kc + 1) & 1) * STAGE_BYTES;
            uint32_t sbb = sa + BM * 128;
            const char* a = gA + (kc + 1) * (BK * 2);
            const char* b = gB + (kc + 1) * (BK * 2);
#pragma unroll
            for (int i = 0; i < 8; i++) CP_ASYNC16(sa + sw0 + i * 2048, a + g0 + (size_t)i * 32768);
#pragma unroll
            for (int i = 0; i < 6; i++) CP_ASYNC16(sbb + sw0 + i * 2048, b + g0 + (size_t)i * 32768);
            CP_ASYNC_COMMIT();
        }

        const uint32_t stg = sb + (kc & 1) * STAGE_BYTES;
        const uint32_t arb = stg + aB0;
        const uint32_t brb = stg + bB0;

#pragma unroll
        for (int ks = 0; ks < 4; ks++) {
            const uint32_t ko = ((uint32_t)ks << 5) ^ swX;
            uint32_t af[4][4];
#pragma unroll
            for (int mt = 0; mt < 4; mt++)
                ldmatrix_x4(af[mt], arb + mt * 2048 + ko);
            uint32_t bf[3][4];
#pragma unroll
            for (int nt = 0; nt < 3; nt++)
                ldmatrix_x4(bf[nt], brb + nt * 2048 + ko);
#pragma unroll
            for (int mt = 0; mt < 4; mt++)
#pragma unroll
                for (int n8 = 0; n8 < 6; n8++) {
                    int nt = n8 >> 1, hi = n8 & 1;
                    mma16816(c[mt][n8], af[mt], bf[nt][hi], bf[nt][2 + hi]);
                }
        }
    }

    // ------- epilogue: +bias, direct float2 stores -------
#pragma unroll
    for (int n8 = 0; n8 < 6; n8++) {
        int n = n0 + wn * 48 + n8 * 8 + ((lane & 3) << 1);
        float bv0 = bias[n], bv1 = bias[n + 1];
#pragma unroll
        for (int mt = 0; mt < 4; mt++) {
            int m = m0 + wm * 64 + mt * 16 + (lane >> 2);
            float2 v0 = make_float2(c[mt][n8][0] + bv0, c[mt][n8][1] + bv1);
            float2 v1 = make_float2(c[mt][n8][2] + bv0, c[mt][n8][3] + bv1);
            *reinterpret_cast<float2*>(out + (size_t)m * N_TOTAL + n) = v0;
            *reinterpret_cast<float2*>(out + (size_t)(m + 8) * N_TOTAL + n) = v1;
        }
    }
}

// ---------------- launch -------------------------------------------------------
extern "C" void kernel_launch(void* const* d_in, const int* in_sizes, int n_in,
                              void* d_out, int out_size) {
    const float* x     = (const float*)d_in[0];
    const float* W_qkv = (const float*)d_in[1];
    const float* b_qkv = (const float*)d_in[2];
    const float* A_q   = (const float*)d_in[3];
    const float* B_q   = (const float*)d_in[4];
    const float* A_k   = (const float*)d_in[5];
    const float* B_k   = (const float*)d_in[6];
    const float* A_v   = (const float*)d_in[7];
    const float* B_v   = (const float*)d_in[8];
    const float* alpha = (const float*)d_in[9];
    float* out = (float*)d_out;

    static bool attr_done = false;
    if (!attr_done) {
        cudaFuncSetAttribute(gemm_kernel, cudaFuncAttributeMaxDynamicSharedMemorySize, GEMM_SMEM);
        attr_done = true;
    }

    prep_kernel<<<WPREP_BLOCKS + CONVERT_BLOCKS, 256>>>(
        x, W_qkv, A_q, B_q, A_k, B_k, A_v, B_v, alpha);
    gemm_kernel<<<dim3(N_TOTAL / BN, M_TOTAL / BM), 128, GEMM_SMEM>>>(b_qkv, out);
}